// round 10
// baseline (speedup 1.0000x reference)
#include <cuda_runtime.h>
#include <math.h>

#define DD 512
#define SS 8192
#define BB 4
#define M_TOTAL (BB*SS)      // 32768
#define SPLITK 8
#define KCHUNK (SS/SPLITK)   // 1024

// Scratch (device globals: allocation-free kernel_launch)
__device__ float g_Q[M_TOTAL*DD];                // silu(rope(XQ@Wq^T+bq))
__device__ float g_V[M_TOTAL*DD];                // silu(XKV@Wv^T+bv)
__device__ float g_K[M_TOTAL*DD];                // silu(rope(XKV@Wv^T+bv))
__device__ float g_P[SPLITK*BB*DD*DD];           // split-K partials of QtV
__device__ float g_QtV[BB*DD*DD];

__device__ __forceinline__ float silu_f(float x) {
    return x / (1.0f + expf(-x));
}

// ---- packed f32x2 helpers (sm_100+ FFMA2 path; ptxas never emits from C++) ----
__device__ __forceinline__ unsigned long long ffma2(unsigned long long a,
                                                    unsigned long long b,
                                                    unsigned long long c) {
    unsigned long long d;
    asm("fma.rn.f32x2 %0, %1, %2, %3;" : "=l"(d) : "l"(a), "l"(b), "l"(c));
    return d;
}
__device__ __forceinline__ unsigned long long dup2(float x) {
    unsigned long long r;
    asm("mov.b64 %0, {%1, %1};" : "=l"(r) : "f"(x));
    return r;
}
__device__ __forceinline__ void unpack2(unsigned long long v, float& lo, float& hi) {
    asm("mov.b64 {%0, %1}, %2;" : "=f"(lo), "=f"(hi) : "l"(v));
}

// ---------------------------------------------------------------------------
// Kernel 1: projections. z=0: Q path, z=1: V/K path.
// GEMM: Y[M=32768, N=512] = X[M,512] @ W^T  (W row-major [512,512])
// 128x128x16 tiles, 256 thr, 8x8 microtile, FFMA2 packed over column pairs.
// ---------------------------------------------------------------------------
__global__ __launch_bounds__(256) void proj_kernel(
    const float* __restrict__ Xq, const float* __restrict__ Xkv,
    const float* __restrict__ Wq, const float* __restrict__ bq,
    const float* __restrict__ Wv, const float* __restrict__ bv)
{
    const int z = blockIdx.z;
    const float* __restrict__ X    = z ? Xkv : Xq;
    const float* __restrict__ W    = z ? Wv  : Wq;
    const float* __restrict__ bias = z ? bv  : bq;

    __shared__ float As[16][132];
    __shared__ float Bs[16][132];

    const int t  = threadIdx.x;
    const int r0 = blockIdx.x * 128;
    const int c0 = blockIdx.y * 128;
    const int tm = t >> 4;          // 0..15
    const int tn = t & 15;          // 0..15

    const int lr = t >> 2;          // 0..63
    const int lk = (t & 3) << 2;    // 0,4,8,12

    unsigned long long acc2[8][4];
#pragma unroll
    for (int i = 0; i < 8; i++)
#pragma unroll
        for (int j = 0; j < 4; j++) acc2[i][j] = 0ULL;

    for (int k0 = 0; k0 < DD; k0 += 16) {
        float4 a0 = *(const float4*)(X + (size_t)(r0 + lr     ) * DD + k0 + lk);
        float4 a1 = *(const float4*)(X + (size_t)(r0 + lr + 64) * DD + k0 + lk);
        float4 w0 = *(const float4*)(W + (size_t)(c0 + lr     ) * DD + k0 + lk);
        float4 w1 = *(const float4*)(W + (size_t)(c0 + lr + 64) * DD + k0 + lk);
        __syncthreads();
        As[lk+0][lr]    = a0.x; As[lk+1][lr]    = a0.y; As[lk+2][lr]    = a0.z; As[lk+3][lr]    = a0.w;
        As[lk+0][lr+64] = a1.x; As[lk+1][lr+64] = a1.y; As[lk+2][lr+64] = a1.z; As[lk+3][lr+64] = a1.w;
        Bs[lk+0][lr]    = w0.x; Bs[lk+1][lr]    = w0.y; Bs[lk+2][lr]    = w0.z; Bs[lk+3][lr]    = w0.w;
        Bs[lk+0][lr+64] = w1.x; Bs[lk+1][lr+64] = w1.y; Bs[lk+2][lr+64] = w1.z; Bs[lk+3][lr+64] = w1.w;
        __syncthreads();
#pragma unroll
        for (int kk = 0; kk < 16; kk++) {
            float4 A0 = *(const float4*)&As[kk][4*tm];
            float4 A1 = *(const float4*)&As[kk][64 + 4*tm];
            ulonglong2 bq0 = *(const ulonglong2*)&Bs[kk][4*tn];        // (b0,b1),(b2,b3)
            ulonglong2 bq1 = *(const ulonglong2*)&Bs[kk][64 + 4*tn];   // (b4,b5),(b6,b7)
            unsigned long long b2[4] = {bq0.x, bq0.y, bq1.x, bq1.y};
            unsigned long long a2[8] = {dup2(A0.x), dup2(A0.y), dup2(A0.z), dup2(A0.w),
                                        dup2(A1.x), dup2(A1.y), dup2(A1.z), dup2(A1.w)};
#pragma unroll
            for (int i = 0; i < 8; i++)
#pragma unroll
                for (int j = 0; j < 4; j++)
                    acc2[i][j] = ffma2(a2[i], b2[j], acc2[i][j]);
        }
    }

    // Epilogue: bias, rope (cols < 64 only, i.e. c0==0 first quad), silu, store.
    const bool doRope = (c0 == 0);
#pragma unroll
    for (int i = 0; i < 8; i++) {
        float acc[8];
#pragma unroll
        for (int j = 0; j < 4; j++) unpack2(acc2[i][j], acc[2*j], acc[2*j+1]);

        const int rfrag = (i < 4) ? (4*tm + i) : (64 + 4*tm + (i - 4));
        const int rowg  = r0 + rfrag;
        const float pos = (float)(rowg & (SS - 1));

        float v0[4], v1[4];
#pragma unroll
        for (int q = 0; q < 4; q++) {
            v0[q] = acc[q]     + bias[c0 + 4*tn + q];
            v1[q] = acc[4 + q] + bias[c0 + 64 + 4*tn + q];
        }

        float rv[4];
        if (doRope) {
#pragma unroll
            for (int p = 0; p < 2; p++) {
                const int fi = 2*tn + p;                       // freq index 0..31
                const float invf = (float)exp(-(double)fi * 0.28782313662425572); // ln(1e4)/32
                const float fr = pos * invf;
                float cs, sn;
                sincosf(fr, &sn, &cs);
                const float a = v0[2*p], b = v0[2*p+1];
                rv[2*p]   = a * cs - b * sn;
                rv[2*p+1] = b * cs + a * sn;
            }
        } else {
#pragma unroll
            for (int q = 0; q < 4; q++) rv[q] = v0[q];
        }

        const size_t off0 = (size_t)rowg * DD + c0 + 4*tn;
        const size_t off1 = off0 + 64;

        if (z == 0) {
            float4 o0 = make_float4(silu_f(rv[0]), silu_f(rv[1]), silu_f(rv[2]), silu_f(rv[3]));
            float4 o1 = make_float4(silu_f(v1[0]), silu_f(v1[1]), silu_f(v1[2]), silu_f(v1[3]));
            *(float4*)(g_Q + off0) = o0;
            *(float4*)(g_Q + off1) = o1;
        } else {
            float4 s1 = make_float4(silu_f(v1[0]), silu_f(v1[1]), silu_f(v1[2]), silu_f(v1[3]));
            float4 sv = make_float4(silu_f(v0[0]), silu_f(v0[1]), silu_f(v0[2]), silu_f(v0[3]));
            float4 sk = make_float4(silu_f(rv[0]), silu_f(rv[1]), silu_f(rv[2]), silu_f(rv[3]));
            *(float4*)(g_V + off0) = sv;
            *(float4*)(g_V + off1) = s1;
            *(float4*)(g_K + off0) = sk;
            *(float4*)(g_K + off1) = s1;   // rope only touches cols < 64
        }
    }
}

// ---------------------------------------------------------------------------
// Kernel 2: QtV partials. QtV[b][d][e] = sum_n Q[b,n,d] * V[b,n,e]
// split-K over n (8 chunks of 1024). 128x128x16 tiles, FFMA2 microtile.
// ---------------------------------------------------------------------------
__global__ __launch_bounds__(256) void qtv_kernel()
{
    const int t  = threadIdx.x;
    const int d0 = blockIdx.x * 128;
    const int e0 = blockIdx.y * 128;
    const int b  = blockIdx.z & 3;
    const int sp = blockIdx.z >> 2;

    const float* __restrict__ Qb = g_Q + (size_t)b * SS * DD;
    const float* __restrict__ Vb = g_V + (size_t)b * SS * DD;

    __shared__ float As[16][132];   // [k][d]
    __shared__ float Bs[16][132];   // [k][e]

    const int tm = t >> 4, tn = t & 15;
    const int lk  = t >> 5;           // 0..7
    const int lc4 = (t & 31) << 2;    // 0..124

    unsigned long long acc2[8][4];
#pragma unroll
    for (int i = 0; i < 8; i++)
#pragma unroll
        for (int j = 0; j < 4; j++) acc2[i][j] = 0ULL;

    const int nEnd = sp * KCHUNK + KCHUNK;
    for (int n = sp * KCHUNK; n < nEnd; n += 16) {
        float4 qa0 = *(const float4*)(Qb + (size_t)(n + lk    ) * DD + d0 + lc4);
        float4 qa1 = *(const float4*)(Qb + (size_t)(n + lk + 8) * DD + d0 + lc4);
        float4 va0 = *(const float4*)(Vb + (size_t)(n + lk    ) * DD + e0 + lc4);
        float4 va1 = *(const float4*)(Vb + (size_t)(n + lk + 8) * DD + e0 + lc4);
        __syncthreads();
        *(float4*)&As[lk    ][lc4] = qa0;
        *(float4*)&As[lk + 8][lc4] = qa1;
        *(float4*)&Bs[lk    ][lc4] = va0;
        *(float4*)&Bs[lk + 8][lc4] = va1;
        __syncthreads();
#pragma unroll
        for (int kk = 0; kk < 16; kk++) {
            float4 A0 = *(const float4*)&As[kk][4*tm];
            float4 A1 = *(const float4*)&As[kk][64 + 4*tm];
            ulonglong2 bq0 = *(const ulonglong2*)&Bs[kk][4*tn];
            ulonglong2 bq1 = *(const ulonglong2*)&Bs[kk][64 + 4*tn];
            unsigned long long b2[4] = {bq0.x, bq0.y, bq1.x, bq1.y};
            unsigned long long a2[8] = {dup2(A0.x), dup2(A0.y), dup2(A0.z), dup2(A0.w),
                                        dup2(A1.x), dup2(A1.y), dup2(A1.z), dup2(A1.w)};
#pragma unroll
            for (int i = 0; i < 8; i++)
#pragma unroll
                for (int j = 0; j < 4; j++)
                    acc2[i][j] = ffma2(a2[i], b2[j], acc2[i][j]);
        }
    }

    float* __restrict__ P = g_P + (size_t)(sp * BB + b) * DD * DD;
#pragma unroll
    for (int i = 0; i < 8; i++) {
        float acc[8];
#pragma unroll
        for (int j = 0; j < 4; j++) unpack2(acc2[i][j], acc[2*j], acc[2*j+1]);
        const int d = d0 + ((i < 4) ? (4*tm + i) : (64 + 4*tm + (i - 4)));
        float4 o0 = make_float4(acc[0], acc[1], acc[2], acc[3]);
        float4 o1 = make_float4(acc[4], acc[5], acc[6], acc[7]);
        *(float4*)(P + (size_t)d * DD + e0 + 4*tn)      = o0;
        *(float4*)(P + (size_t)d * DD + e0 + 64 + 4*tn) = o1;
    }
}

__global__ __launch_bounds__(256) void reduce_kernel()
{
    const int i4 = (blockIdx.x * 256 + threadIdx.x) * 4;   // < BB*DD*DD = 1048576
    float4 s = make_float4(0.f, 0.f, 0.f, 0.f);
#pragma unroll
    for (int sp = 0; sp < SPLITK; sp++) {
        float4 p = *(const float4*)(g_P + (size_t)sp * (BB*DD*DD) + i4);
        s.x += p.x; s.y += p.y; s.z += p.z; s.w += p.w;
    }
    *(float4*)(g_QtV + i4) = s;
}

// ---------------------------------------------------------------------------
// Kernel 3: out[n,e] = sum_d K[n,d] * QtV[b][d][e], fused GroupNorm (8 groups
// of 64 channels). Block = 32 rows x all 512 cols; thread = 4 rows x 16 cols
// (4 quads at stride 128, each quad inside one group -> 16-lane shfl stats).
// FFMA2 packed over column pairs.
// ---------------------------------------------------------------------------
__global__ __launch_bounds__(256) void out_kernel(
    const float* __restrict__ gn_w, const float* __restrict__ gn_b,
    float* __restrict__ out)
{
    const int r0 = blockIdx.x * 32;
    const int b  = r0 >> 13;   // /8192
    const float* __restrict__ QtVb = g_QtV + (size_t)b * DD * DD;

    __shared__ float As[16][36];     // [k][row]
    __shared__ float Bs[16][512];    // [k][e]

    const int t  = threadIdx.x;
    const int tm = t >> 5;   // 0..7  (warp id -> row group)
    const int tn = t & 31;   // lane -> col group

    unsigned long long acc2[4][8];
#pragma unroll
    for (int i = 0; i < 4; i++)
#pragma unroll
        for (int j = 0; j < 8; j++) acc2[i][j] = 0ULL;

    const int ar = t >> 2;            // 0..63 (only t<128 used)
    const int ak = (t & 3) << 2;

    for (int k0 = 0; k0 < DD; k0 += 16) {
        float4 av = make_float4(0.f, 0.f, 0.f, 0.f);
        if (t < 128)
            av = *(const float4*)(g_K + (size_t)(r0 + ar) * DD + k0 + ak);
        float4 bl[8];
#pragma unroll
        for (int p = 0; p < 8; p++) {
            const int fid = t + 256 * p;
            const int k   = fid >> 7;
            const int e4  = fid & 127;
            bl[p] = *(const float4*)(QtVb + (size_t)(k0 + k) * DD + 4 * e4);
        }
        __syncthreads();
        if (t < 128) {
            As[ak+0][ar] = av.x; As[ak+1][ar] = av.y;
            As[ak+2][ar] = av.z; As[ak+3][ar] = av.w;
        }
#pragma unroll
        for (int p = 0; p < 8; p++) {
            const int fid = t + 256 * p;
            const int k   = fid >> 7;
            const int e4  = fid & 127;
            *(float4*)&Bs[k][4 * e4] = bl[p];
        }
        __syncthreads();
#pragma unroll
        for (int kk = 0; kk < 16; kk++) {
            float4 A = *(const float4*)&As[kk][4 * tm];
            unsigned long long a2[4] = {dup2(A.x), dup2(A.y), dup2(A.z), dup2(A.w)};
            unsigned long long b2[8];
#pragma unroll
            for (int jq = 0; jq < 4; jq++) {
                ulonglong2 bqv = *(const ulonglong2*)&Bs[kk][128 * jq + 4 * tn];
                b2[2*jq]   = bqv.x;
                b2[2*jq+1] = bqv.y;
            }
#pragma unroll
            for (int i = 0; i < 4; i++)
#pragma unroll
                for (int j = 0; j < 8; j++)
                    acc2[i][j] = ffma2(a2[i], b2[j], acc2[i][j]);
        }
    }

    // GroupNorm: per row, group g covers cols [64g, 64g+64).
    // Thread quad (jq) cols = 128*jq + 4*tn + {0..3} -> group 2*jq + (tn>=16).
    // Two-pass (mean, then centered variance) for numerical safety.
    const unsigned FULL = 0xffffffffu;
#pragma unroll
    for (int i = 0; i < 4; i++) {
        float acc[16];
#pragma unroll
        for (int j = 0; j < 8; j++) unpack2(acc2[i][j], acc[2*j], acc[2*j+1]);

        const int rowg = r0 + 4 * tm + i;
        float mu[4], inv[4];
#pragma unroll
        for (int j = 0; j < 4; j++) {
            float s = acc[4*j] + acc[4*j+1] + acc[4*j+2] + acc[4*j+3];
            s += __shfl_xor_sync(FULL, s, 1);
            s += __shfl_xor_sync(FULL, s, 2);
            s += __shfl_xor_sync(FULL, s, 4);
            s += __shfl_xor_sync(FULL, s, 8);
            mu[j] = s * (1.0f / 64.0f);
        }
#pragma unroll
        for (int j = 0; j < 4; j++) {
            float sq = 0.0f;
#pragma unroll
            for (int q = 0; q < 4; q++) {
                const float d2 = acc[4*j + q] - mu[j];
                sq = fmaf(d2, d2, sq);
            }
            sq += __shfl_xor_sync(FULL, sq, 1);
            sq += __shfl_xor_sync(FULL, sq, 2);
            sq += __shfl_xor_sync(FULL, sq, 4);
            sq += __shfl_xor_sync(FULL, sq, 8);
            inv[j] = rsqrtf(sq * (1.0f / 64.0f) + 1e-6f);
        }
#pragma unroll
        for (int j = 0; j < 4; j++) {
            const int c = 128 * j + 4 * tn;
            float4 o;
            o.x = (acc[4*j+0] - mu[j]) * inv[j] * gn_w[c+0] + gn_b[c+0];
            o.y = (acc[4*j+1] - mu[j]) * inv[j] * gn_w[c+1] + gn_b[c+1];
            o.z = (acc[4*j+2] - mu[j]) * inv[j] * gn_w[c+2] + gn_b[c+2];
            o.w = (acc[4*j+3] - mu[j]) * inv[j] * gn_w[c+3] + gn_b[c+3];
            *(float4*)(out + (size_t)rowg * DD + c) = o;
        }
    }
}

__global__ void tail_kernel(const float* __restrict__ S_h,
                            const float* __restrict__ S_C,
                            float* __restrict__ out, int out_size)
{
    if (threadIdx.x == 0 && blockIdx.x == 0) {
        const int base = M_TOTAL * DD;
        if (out_size > base)     out[base]     = S_h[0];
        if (out_size > base + 1) out[base + 1] = S_C[0];
    }
}

extern "C" void kernel_launch(void* const* d_in, const int* in_sizes, int n_in,
                              void* d_out, int out_size)
{
    const float* Xq  = (const float*)d_in[0];
    const float* Xkv = (const float*)d_in[1];
    const float* Sh  = (const float*)d_in[2];
    const float* Sc  = (const float*)d_in[3];
    const float* Wq  = (const float*)d_in[4];
    const float* bq  = (const float*)d_in[5];
    // d_in[6]=Wk, d_in[7]=bk are dead in the reference
    const float* Wv  = (const float*)d_in[8];
    const float* bv  = (const float*)d_in[9];
    const float* gw  = (const float*)d_in[10];
    const float* gb  = (const float*)d_in[11];
    float* out = (float*)d_out;

    dim3 gp(M_TOTAL / 128, DD / 128, 2);
    proj_kernel<<<gp, 256>>>(Xq, Xkv, Wq, bq, Wv, bv);

    dim3 gq(DD / 128, DD / 128, BB * SPLITK);
    qtv_kernel<<<gq, 256>>>();

    reduce_kernel<<<(BB * DD * DD) / 1024, 256>>>();

    out_kernel<<<M_TOTAL / 32, 256>>>(gw, gb, out);

    tail_kernel<<<1, 32>>>(Sh, Sc, out, out_size);
}

// round 11
// speedup vs baseline: 1.1032x; 1.1032x over previous
#include <cuda_runtime.h>
#include <math.h>

#define DD 512
#define SS 8192
#define BB 4
#define M_TOTAL (BB*SS)      // 32768
#define SPLITK 8
#define KCHUNK (SS/SPLITK)   // 1024

// Scratch (device globals: allocation-free kernel_launch)
__device__ float g_Q[M_TOTAL*DD];                // silu(rope(XQ@Wq^T+bq))
__device__ float g_V[M_TOTAL*DD];                // silu(XKV@Wv^T+bv)
__device__ float g_K[M_TOTAL*DD];                // silu(rope(XKV@Wv^T+bv))
__device__ float g_P[SPLITK*BB*DD*DD];           // split-K partials of QtV
__device__ float g_QtV[BB*DD*DD];

__device__ __forceinline__ float silu_f(float x) {
    return x / (1.0f + expf(-x));
}

// ---- packed f32x2 helpers (sm_100+ FFMA2 path; ptxas never emits from C++) ----
__device__ __forceinline__ unsigned long long ffma2(unsigned long long a,
                                                    unsigned long long b,
                                                    unsigned long long c) {
    unsigned long long d;
    asm("fma.rn.f32x2 %0, %1, %2, %3;" : "=l"(d) : "l"(a), "l"(b), "l"(c));
    return d;
}
__device__ __forceinline__ unsigned long long dup2(float x) {
    unsigned long long r;
    asm("mov.b64 %0, {%1, %1};" : "=l"(r) : "f"(x));
    return r;
}
__device__ __forceinline__ void unpack2(unsigned long long v, float& lo, float& hi) {
    asm("mov.b64 {%0, %1}, %2;" : "=f"(lo), "=f"(hi) : "l"(v));
}

// ---- cp.async helpers (16B, L1-bypass) ----
__device__ __forceinline__ void cp_async16(void* smem, const void* gmem) {
    unsigned saddr = (unsigned)__cvta_generic_to_shared(smem);
    asm volatile("cp.async.cg.shared.global [%0], [%1], 16;" :: "r"(saddr), "l"(gmem));
}
__device__ __forceinline__ void cp_commit() {
    asm volatile("cp.async.commit_group;");
}
__device__ __forceinline__ void cp_wait0() {
    asm volatile("cp.async.wait_group 0;");
}
__device__ __forceinline__ void cp_wait1() {
    asm volatile("cp.async.wait_group 1;");
}

// ---------------------------------------------------------------------------
// Kernel 1: projections. z=0: Q path, z=1: V/K path.
// GEMM: Y[M=32768, N=512] = X[M,512] @ W^T  (W row-major [512,512])
// 128x128x16 tiles, 256 thr, 8x8 microtile, FFMA2 packed over column pairs.
// ---------------------------------------------------------------------------
__global__ __launch_bounds__(256) void proj_kernel(
    const float* __restrict__ Xq, const float* __restrict__ Xkv,
    const float* __restrict__ Wq, const float* __restrict__ bq,
    const float* __restrict__ Wv, const float* __restrict__ bv)
{
    const int z = blockIdx.z;
    const float* __restrict__ X    = z ? Xkv : Xq;
    const float* __restrict__ W    = z ? Wv  : Wq;
    const float* __restrict__ bias = z ? bv  : bq;

    __shared__ float As[16][132];
    __shared__ float Bs[16][132];

    const int t  = threadIdx.x;
    const int r0 = blockIdx.x * 128;
    const int c0 = blockIdx.y * 128;
    const int tm = t >> 4;          // 0..15
    const int tn = t & 15;          // 0..15

    const int lr = t >> 2;          // 0..63
    const int lk = (t & 3) << 2;    // 0,4,8,12

    unsigned long long acc2[8][4];
#pragma unroll
    for (int i = 0; i < 8; i++)
#pragma unroll
        for (int j = 0; j < 4; j++) acc2[i][j] = 0ULL;

    for (int k0 = 0; k0 < DD; k0 += 16) {
        float4 a0 = *(const float4*)(X + (size_t)(r0 + lr     ) * DD + k0 + lk);
        float4 a1 = *(const float4*)(X + (size_t)(r0 + lr + 64) * DD + k0 + lk);
        float4 w0 = *(const float4*)(W + (size_t)(c0 + lr     ) * DD + k0 + lk);
        float4 w1 = *(const float4*)(W + (size_t)(c0 + lr + 64) * DD + k0 + lk);
        __syncthreads();
        As[lk+0][lr]    = a0.x; As[lk+1][lr]    = a0.y; As[lk+2][lr]    = a0.z; As[lk+3][lr]    = a0.w;
        As[lk+0][lr+64] = a1.x; As[lk+1][lr+64] = a1.y; As[lk+2][lr+64] = a1.z; As[lk+3][lr+64] = a1.w;
        Bs[lk+0][lr]    = w0.x; Bs[lk+1][lr]    = w0.y; Bs[lk+2][lr]    = w0.z; Bs[lk+3][lr]    = w0.w;
        Bs[lk+0][lr+64] = w1.x; Bs[lk+1][lr+64] = w1.y; Bs[lk+2][lr+64] = w1.z; Bs[lk+3][lr+64] = w1.w;
        __syncthreads();
#pragma unroll
        for (int kk = 0; kk < 16; kk++) {
            float4 A0 = *(const float4*)&As[kk][4*tm];
            float4 A1 = *(const float4*)&As[kk][64 + 4*tm];
            ulonglong2 bq0 = *(const ulonglong2*)&Bs[kk][4*tn];        // (b0,b1),(b2,b3)
            ulonglong2 bq1 = *(const ulonglong2*)&Bs[kk][64 + 4*tn];   // (b4,b5),(b6,b7)
            unsigned long long b2[4] = {bq0.x, bq0.y, bq1.x, bq1.y};
            unsigned long long a2[8] = {dup2(A0.x), dup2(A0.y), dup2(A0.z), dup2(A0.w),
                                        dup2(A1.x), dup2(A1.y), dup2(A1.z), dup2(A1.w)};
#pragma unroll
            for (int i = 0; i < 8; i++)
#pragma unroll
                for (int j = 0; j < 4; j++)
                    acc2[i][j] = ffma2(a2[i], b2[j], acc2[i][j]);
        }
    }

    // Epilogue: bias, rope (cols < 64 only, i.e. c0==0 first quad), silu, store.
    const bool doRope = (c0 == 0);
#pragma unroll
    for (int i = 0; i < 8; i++) {
        float acc[8];
#pragma unroll
        for (int j = 0; j < 4; j++) unpack2(acc2[i][j], acc[2*j], acc[2*j+1]);

        const int rfrag = (i < 4) ? (4*tm + i) : (64 + 4*tm + (i - 4));
        const int rowg  = r0 + rfrag;
        const float pos = (float)(rowg & (SS - 1));

        float v0[4], v1[4];
#pragma unroll
        for (int q = 0; q < 4; q++) {
            v0[q] = acc[q]     + bias[c0 + 4*tn + q];
            v1[q] = acc[4 + q] + bias[c0 + 64 + 4*tn + q];
        }

        float rv[4];
        if (doRope) {
#pragma unroll
            for (int p = 0; p < 2; p++) {
                const int fi = 2*tn + p;                       // freq index 0..31
                const float invf = (float)exp(-(double)fi * 0.28782313662425572); // ln(1e4)/32
                const float fr = pos * invf;
                float cs, sn;
                sincosf(fr, &sn, &cs);
                const float a = v0[2*p], b = v0[2*p+1];
                rv[2*p]   = a * cs - b * sn;
                rv[2*p+1] = b * cs + a * sn;
            }
        } else {
#pragma unroll
            for (int q = 0; q < 4; q++) rv[q] = v0[q];
        }

        const size_t off0 = (size_t)rowg * DD + c0 + 4*tn;
        const size_t off1 = off0 + 64;

        if (z == 0) {
            float4 o0 = make_float4(silu_f(rv[0]), silu_f(rv[1]), silu_f(rv[2]), silu_f(rv[3]));
            float4 o1 = make_float4(silu_f(v1[0]), silu_f(v1[1]), silu_f(v1[2]), silu_f(v1[3]));
            *(float4*)(g_Q + off0) = o0;
            *(float4*)(g_Q + off1) = o1;
        } else {
            float4 s1 = make_float4(silu_f(v1[0]), silu_f(v1[1]), silu_f(v1[2]), silu_f(v1[3]));
            float4 sv = make_float4(silu_f(v0[0]), silu_f(v0[1]), silu_f(v0[2]), silu_f(v0[3]));
            float4 sk = make_float4(silu_f(rv[0]), silu_f(rv[1]), silu_f(rv[2]), silu_f(rv[3]));
            *(float4*)(g_V + off0) = sv;
            *(float4*)(g_V + off1) = s1;
            *(float4*)(g_K + off0) = sk;
            *(float4*)(g_K + off1) = s1;   // rope only touches cols < 64
        }
    }
}

// ---------------------------------------------------------------------------
// Kernel 2: QtV partials. QtV[b][d][e] = sum_n Q[b,n,d] * V[b,n,e]
// split-K over n (8 chunks of 1024). 128x128x16 tiles, FFMA2 microtile,
// 2-stage cp.async double-buffered pipeline (no transpose needed).
// ---------------------------------------------------------------------------
__global__ __launch_bounds__(256, 2) void qtv_kernel()
{
    const int t  = threadIdx.x;
    const int d0 = blockIdx.x * 128;
    const int e0 = blockIdx.y * 128;
    const int b  = blockIdx.z & 3;
    const int sp = blockIdx.z >> 2;

    const float* __restrict__ Qb = g_Q + (size_t)b * SS * DD;
    const float* __restrict__ Vb = g_V + (size_t)b * SS * DD;

    __shared__ float As[2][16][132];   // [stage][k][d]
    __shared__ float Bs[2][16][132];   // [stage][k][e]

    const int tm = t >> 4, tn = t & 15;
    const int lk  = t >> 5;           // 0..7
    const int lc4 = (t & 31) << 2;    // 0..124

    unsigned long long acc2[8][4];
#pragma unroll
    for (int i = 0; i < 8; i++)
#pragma unroll
        for (int j = 0; j < 4; j++) acc2[i][j] = 0ULL;

    const int n0 = sp * KCHUNK;
    const int NIT = KCHUNK / 16;   // 64

    // prologue: fill stage 0
    {
        const int n = n0;
        cp_async16(&As[0][lk    ][lc4], Qb + (size_t)(n + lk    ) * DD + d0 + lc4);
        cp_async16(&As[0][lk + 8][lc4], Qb + (size_t)(n + lk + 8) * DD + d0 + lc4);
        cp_async16(&Bs[0][lk    ][lc4], Vb + (size_t)(n + lk    ) * DD + e0 + lc4);
        cp_async16(&Bs[0][lk + 8][lc4], Vb + (size_t)(n + lk + 8) * DD + e0 + lc4);
        cp_commit();
    }

    for (int it = 0; it < NIT; it++) {
        const int cur = it & 1;
        if (it + 1 < NIT) {
            const int nxt = (it + 1) & 1;
            const int n = n0 + (it + 1) * 16;
            cp_async16(&As[nxt][lk    ][lc4], Qb + (size_t)(n + lk    ) * DD + d0 + lc4);
            cp_async16(&As[nxt][lk + 8][lc4], Qb + (size_t)(n + lk + 8) * DD + d0 + lc4);
            cp_async16(&Bs[nxt][lk    ][lc4], Vb + (size_t)(n + lk    ) * DD + e0 + lc4);
            cp_async16(&Bs[nxt][lk + 8][lc4], Vb + (size_t)(n + lk + 8) * DD + e0 + lc4);
            cp_commit();
            cp_wait1();
        } else {
            cp_wait0();
        }
        __syncthreads();
#pragma unroll
        for (int kk = 0; kk < 16; kk++) {
            float4 A0 = *(const float4*)&As[cur][kk][4*tm];
            float4 A1 = *(const float4*)&As[cur][kk][64 + 4*tm];
            ulonglong2 bq0 = *(const ulonglong2*)&Bs[cur][kk][4*tn];
            ulonglong2 bq1 = *(const ulonglong2*)&Bs[cur][kk][64 + 4*tn];
            unsigned long long b2[4] = {bq0.x, bq0.y, bq1.x, bq1.y};
            unsigned long long a2[8] = {dup2(A0.x), dup2(A0.y), dup2(A0.z), dup2(A0.w),
                                        dup2(A1.x), dup2(A1.y), dup2(A1.z), dup2(A1.w)};
#pragma unroll
            for (int i = 0; i < 8; i++)
#pragma unroll
                for (int j = 0; j < 4; j++)
                    acc2[i][j] = ffma2(a2[i], b2[j], acc2[i][j]);
        }
        __syncthreads();
    }

    float* __restrict__ P = g_P + (size_t)(sp * BB + b) * DD * DD;
#pragma unroll
    for (int i = 0; i < 8; i++) {
        float acc[8];
#pragma unroll
        for (int j = 0; j < 4; j++) unpack2(acc2[i][j], acc[2*j], acc[2*j+1]);
        const int d = d0 + ((i < 4) ? (4*tm + i) : (64 + 4*tm + (i - 4)));
        float4 o0 = make_float4(acc[0], acc[1], acc[2], acc[3]);
        float4 o1 = make_float4(acc[4], acc[5], acc[6], acc[7]);
        *(float4*)(P + (size_t)d * DD + e0 + 4*tn)      = o0;
        *(float4*)(P + (size_t)d * DD + e0 + 64 + 4*tn) = o1;
    }
}

__global__ __launch_bounds__(256) void reduce_kernel()
{
    const int i4 = (blockIdx.x * 256 + threadIdx.x) * 4;   // < BB*DD*DD = 1048576
    float4 s = make_float4(0.f, 0.f, 0.f, 0.f);
#pragma unroll
    for (int sp = 0; sp < SPLITK; sp++) {
        float4 p = *(const float4*)(g_P + (size_t)sp * (BB*DD*DD) + i4);
        s.x += p.x; s.y += p.y; s.z += p.z; s.w += p.w;
    }
    *(float4*)(g_QtV + i4) = s;
}

// ---------------------------------------------------------------------------
// Kernel 3: out[n,e] = sum_d K[n,d] * QtV[b][d][e], fused GroupNorm (8 groups
// of 64 channels). Block = 32 rows x all 512 cols; thread = 4 rows x 16 cols
// (4 quads at stride 128, each quad inside one group -> 16-lane shfl stats).
// FFMA2 packed; Bs filled via cp.async (kills 32-reg staging -> 2 CTAs/SM).
// ---------------------------------------------------------------------------
__global__ __launch_bounds__(256, 2) void out_kernel(
    const float* __restrict__ gn_w, const float* __restrict__ gn_b,
    float* __restrict__ out)
{
    const int r0 = blockIdx.x * 32;
    const int b  = r0 >> 13;   // /8192
    const float* __restrict__ QtVb = g_QtV + (size_t)b * DD * DD;

    __shared__ float As[16][36];     // [k][row]
    __shared__ float Bs[16][512];    // [k][e]

    const int t  = threadIdx.x;
    const int tm = t >> 5;   // 0..7  (warp id -> row group)
    const int tn = t & 31;   // lane -> col group

    unsigned long long acc2[4][8];
#pragma unroll
    for (int i = 0; i < 4; i++)
#pragma unroll
        for (int j = 0; j < 8; j++) acc2[i][j] = 0ULL;

    const int ar = t >> 2;            // 0..63 (only t<128 used)
    const int ak = (t & 3) << 2;

    for (int k0 = 0; k0 < DD; k0 += 16) {
        float4 av = make_float4(0.f, 0.f, 0.f, 0.f);
        if (t < 128)
            av = *(const float4*)(g_K + (size_t)(r0 + ar) * DD + k0 + ak);
        __syncthreads();   // previous iteration's reads of As/Bs are done
#pragma unroll
        for (int p = 0; p < 8; p++) {
            const int fid = t + 256 * p;
            const int k   = fid >> 7;
            const int e4  = fid & 127;
            cp_async16(&Bs[k][4 * e4], QtVb + (size_t)(k0 + k) * DD + 4 * e4);
        }
        cp_commit();
        if (t < 128) {
            As[ak+0][ar] = av.x; As[ak+1][ar] = av.y;
            As[ak+2][ar] = av.z; As[ak+3][ar] = av.w;
        }
        cp_wait0();
        __syncthreads();
#pragma unroll
        for (int kk = 0; kk < 16; kk++) {
            float4 A = *(const float4*)&As[kk][4 * tm];
            unsigned long long a2[4] = {dup2(A.x), dup2(A.y), dup2(A.z), dup2(A.w)};
            unsigned long long b2[8];
#pragma unroll
            for (int jq = 0; jq < 4; jq++) {
                ulonglong2 bqv = *(const ulonglong2*)&Bs[kk][128 * jq + 4 * tn];
                b2[2*jq]   = bqv.x;
                b2[2*jq+1] = bqv.y;
            }
#pragma unroll
            for (int i = 0; i < 4; i++)
#pragma unroll
                for (int j = 0; j < 8; j++)
                    acc2[i][j] = ffma2(a2[i], b2[j], acc2[i][j]);
        }
    }

    // GroupNorm: per row, group g covers cols [64g, 64g+64).
    // Thread quad (jq) cols = 128*jq + 4*tn + {0..3} -> group 2*jq + (tn>=16).
    // Two-pass (mean, then centered variance) for numerical safety.
    const unsigned FULL = 0xffffffffu;
#pragma unroll
    for (int i = 0; i < 4; i++) {
        float acc[16];
#pragma unroll
        for (int j = 0; j < 8; j++) unpack2(acc2[i][j], acc[2*j], acc[2*j+1]);

        const int rowg = r0 + 4 * tm + i;
        float mu[4], inv[4];
#pragma unroll
        for (int j = 0; j < 4; j++) {
            float s = acc[4*j] + acc[4*j+1] + acc[4*j+2] + acc[4*j+3];
            s += __shfl_xor_sync(FULL, s, 1);
            s += __shfl_xor_sync(FULL, s, 2);
            s += __shfl_xor_sync(FULL, s, 4);
            s += __shfl_xor_sync(FULL, s, 8);
            mu[j] = s * (1.0f / 64.0f);
        }
#pragma unroll
        for (int j = 0; j < 4; j++) {
            float sq = 0.0f;
#pragma unroll
            for (int q = 0; q < 4; q++) {
                const float d2 = acc[4*j + q] - mu[j];
                sq = fmaf(d2, d2, sq);
            }
            sq += __shfl_xor_sync(FULL, sq, 1);
            sq += __shfl_xor_sync(FULL, sq, 2);
            sq += __shfl_xor_sync(FULL, sq, 4);
            sq += __shfl_xor_sync(FULL, sq, 8);
            inv[j] = rsqrtf(sq * (1.0f / 64.0f) + 1e-6f);
        }
#pragma unroll
        for (int j = 0; j < 4; j++) {
            const int c = 128 * j + 4 * tn;
            float4 o;
            o.x = (acc[4*j+0] - mu[j]) * inv[j] * gn_w[c+0] + gn_b[c+0];
            o.y = (acc[4*j+1] - mu[j]) * inv[j] * gn_w[c+1] + gn_b[c+1];
            o.z = (acc[4*j+2] - mu[j]) * inv[j] * gn_w[c+2] + gn_b[c+2];
            o.w = (acc[4*j+3] - mu[j]) * inv[j] * gn_w[c+3] + gn_b[c+3];
            *(float4*)(out + (size_t)rowg * DD + c) = o;
        }
    }
}

__global__ void tail_kernel(const float* __restrict__ S_h,
                            const float* __restrict__ S_C,
                            float* __restrict__ out, int out_size)
{
    if (threadIdx.x == 0 && blockIdx.x == 0) {
        const int base = M_TOTAL * DD;
        if (out_size > base)     out[base]     = S_h[0];
        if (out_size > base + 1) out[base + 1] = S_C[0];
    }
}

extern "C" void kernel_launch(void* const* d_in, const int* in_sizes, int n_in,
                              void* d_out, int out_size)
{
    const float* Xq  = (const float*)d_in[0];
    const float* Xkv = (const float*)d_in[1];
    const float* Sh  = (const float*)d_in[2];
    const float* Sc  = (const float*)d_in[3];
    const float* Wq  = (const float*)d_in[4];
    const float* bq  = (const float*)d_in[5];
    // d_in[6]=Wk, d_in[7]=bk are dead in the reference
    const float* Wv  = (const float*)d_in[8];
    const float* bv  = (const float*)d_in[9];
    const float* gw  = (const float*)d_in[10];
    const float* gb  = (const float*)d_in[11];
    float* out = (float*)d_out;

    dim3 gp(M_TOTAL / 128, DD / 128, 2);
    proj_kernel<<<gp, 256>>>(Xq, Xkv, Wq, bq, Wv, bv);

    dim3 gq(DD / 128, DD / 128, BB * SPLITK);
    qtv_kernel<<<gq, 256>>>();

    reduce_kernel<<<(BB * DD * DD) / 1024, 256>>>();

    out_kernel<<<M_TOTAL / 32, 256>>>(gw, gb, out);

    tail_kernel<<<1, 32>>>(Sh, Sc, out, out_size);
}